// round 1
// baseline (speedup 1.0000x reference)
#include <cuda_runtime.h>

#define NN 262144
#define EE 4194304
#define GG 1024

// ---------------- scratch (device globals; no allocation allowed) ----------
__device__ __align__(16) float g_deg [NN];
__device__ __align__(16) float g_dinv[NN];
__device__ __align__(16) float g_norm[EE];
__device__ __align__(16) float g_agg3[NN * 4];    // layer-1 aggregated raw-x features (padded 3->4)
__device__ __align__(16) float g_out1[NN * 16];   // layer-1 output
__device__ __align__(16) float g_agg2[NN * 16];   // layer-2 aggregate
__device__ __align__(16) float g_pool[GG * 16];   // pooled sums
__device__ __align__(16) float g_cnt [GG];        // node counts per graph

__device__ __forceinline__ void red_add_v4(float* p, float a, float b, float c, float d) {
    asm volatile("red.global.add.v4.f32 [%0], {%1,%2,%3,%4};"
                 :: "l"(p), "f"(a), "f"(b), "f"(c), "f"(d) : "memory");
}

__device__ __forceinline__ float leaky(float x) { return x > 0.0f ? x : 0.01f * x; }

// ---------------- K0: zero all scratch ------------------------------------
__global__ void k_zero() {
    int t = blockIdx.x * blockDim.x + threadIdx.x;   // NN*4 threads (float4 granularity)
    float4 z = make_float4(0.f, 0.f, 0.f, 0.f);
    ((float4*)g_agg2)[t] = z;                         // NN*4 float4s
    if (t < NN)        ((float4*)g_agg3)[t] = z;      // NN   float4s
    if (t < NN / 4)    ((float4*)g_deg )[t] = z;
    if (t < GG * 4)    ((float4*)g_pool)[t] = z;
    if (t < GG / 4)    ((float4*)g_cnt )[t] = z;
}

// ---------------- K1: degree accumulation ----------------------------------
__global__ void k_deg(const int* __restrict__ dst, const float* __restrict__ ew) {
    int e = blockIdx.x * blockDim.x + threadIdx.x;
    if (e < EE) atomicAdd(&g_deg[dst[e]], ew[e]);
}

// ---------------- K2: dinv = deg^{-1/2} (incl. self-loop +1) ---------------
__global__ void k_dinv() {
    int i = blockIdx.x * blockDim.x + threadIdx.x;
    if (i < NN) g_dinv[i] = rsqrtf(g_deg[i] + 1.0f);
}

// ---------------- K3: norm + layer-1 scatter in raw-feature space ----------
// segment_sum((x@W)*norm) == segment_sum(x*norm)@W  -> scatter 3 feats only.
__global__ void k_l1(const int* __restrict__ src, const int* __restrict__ dst,
                     const float* __restrict__ ew, const float* __restrict__ X) {
    int e = blockIdx.x * blockDim.x + threadIdx.x;
    if (e >= EE) return;
    int s = src[e], d = dst[e];
    float nrm = g_dinv[s] * ew[e] * g_dinv[d];
    g_norm[e] = nrm;
    float x0 = __ldg(X + s * 3 + 0);
    float x1 = __ldg(X + s * 3 + 1);
    float x2 = __ldg(X + s * 3 + 2);
    red_add_v4(g_agg3 + d * 4, x0 * nrm, x1 * nrm, x2 * nrm, 0.0f);
}

// ---------------- K4: out1 = leaky((agg3 + x*dinv^2) @ W1 + b1) ------------
__global__ void k_out1(const float* __restrict__ X,
                       const float* __restrict__ W1, const float* __restrict__ b1) {
    int i = blockIdx.x * blockDim.x + threadIdx.x;
    if (i >= NN) return;
    float di = g_dinv[i], d2 = di * di;
    float a0 = g_agg3[i * 4 + 0] + X[i * 3 + 0] * d2;
    float a1 = g_agg3[i * 4 + 1] + X[i * 3 + 1] * d2;
    float a2 = g_agg3[i * 4 + 2] + X[i * 3 + 2] * d2;
    float o[16];
    #pragma unroll
    for (int f = 0; f < 16; f++) {
        float v = __ldg(b1 + f)
                + a0 * __ldg(W1 + 0 * 16 + f)
                + a1 * __ldg(W1 + 1 * 16 + f)
                + a2 * __ldg(W1 + 2 * 16 + f);
        o[f] = leaky(v);
    }
    float4* dstp = (float4*)(g_out1 + i * 16);
    #pragma unroll
    for (int q = 0; q < 4; q++)
        dstp[q] = make_float4(o[q * 4 + 0], o[q * 4 + 1], o[q * 4 + 2], o[q * 4 + 3]);
}

// ---------------- K5: layer-2 scatter (4 threads/edge, red.v4) -------------
__global__ void k_l2scat(const int* __restrict__ src, const int* __restrict__ dst) {
    int t = blockIdx.x * blockDim.x + threadIdx.x;   // EE*4 threads
    int e = t >> 2, q = t & 3;
    if (e >= EE) return;
    int s = src[e], d = dst[e];
    float nrm = g_norm[e];
    float4 h = ((const float4*)g_out1)[s * 4 + q];
    red_add_v4(g_agg2 + d * 16 + q * 4, h.x * nrm, h.y * nrm, h.z * nrm, h.w * nrm);
}

// ---------------- K6: out2 + mean-pool scatter -----------------------------
__global__ void k_out2pool(const float* __restrict__ W2, const float* __restrict__ b2,
                           const int* __restrict__ batch) {
    __shared__ float sW[256], sb[16];
    int tid = threadIdx.x;
    if (tid < 256) sW[tid] = W2[tid];
    if (tid < 16)  sb[tid] = b2[tid];
    __syncthreads();

    int i = blockIdx.x * blockDim.x + tid;
    if (i >= NN) return;
    float di = g_dinv[i], d2 = di * di;

    float a[16];
    const float4* p2 = (const float4*)(g_agg2 + i * 16);
    const float4* p1 = (const float4*)(g_out1 + i * 16);
    #pragma unroll
    for (int q = 0; q < 4; q++) {
        float4 v2 = p2[q], v1 = p1[q];
        a[q * 4 + 0] = v2.x + v1.x * d2;
        a[q * 4 + 1] = v2.y + v1.y * d2;
        a[q * 4 + 2] = v2.z + v1.z * d2;
        a[q * 4 + 3] = v2.w + v1.w * d2;
    }
    float o[16];
    #pragma unroll
    for (int f = 0; f < 16; f++) {
        float v = sb[f];
        #pragma unroll
        for (int k = 0; k < 16; k++) v += a[k] * sW[k * 16 + f];
        o[f] = leaky(v);
    }
    int b = batch[i];
    float* pp = g_pool + b * 16;
    red_add_v4(pp +  0, o[0],  o[1],  o[2],  o[3]);
    red_add_v4(pp +  4, o[4],  o[5],  o[6],  o[7]);
    red_add_v4(pp +  8, o[8],  o[9],  o[10], o[11]);
    red_add_v4(pp + 12, o[12], o[13], o[14], o[15]);
    atomicAdd(&g_cnt[b], 1.0f);
}

// ---------------- K7: per-graph MLP heads ----------------------------------
__device__ __forceinline__ void layer16x16(const float* in, float* out,
                                           const float* W, const float* b, bool act) {
    #pragma unroll
    for (int f = 0; f < 16; f++) {
        float v = __ldg(b + f);
        #pragma unroll
        for (int k = 0; k < 16; k++) v += in[k] * __ldg(W + k * 16 + f);
        out[f] = act ? leaky(v) : v;
    }
}

__global__ void k_head(const float* __restrict__ Wp1, const float* __restrict__ bp1,
                       const float* __restrict__ Wp2, const float* __restrict__ bp2,
                       const float* __restrict__ Wp3, const float* __restrict__ bp3,
                       const float* __restrict__ Wt1, const float* __restrict__ bt1,
                       const float* __restrict__ Wt2, const float* __restrict__ bt2,
                       const float* __restrict__ Wt3, const float* __restrict__ bt3,
                       float* __restrict__ out) {
    int g = blockIdx.x * blockDim.x + threadIdx.x;
    if (g >= GG) return;
    float inv = 1.0f / fmaxf(g_cnt[g], 1.0f);
    float p[16], t1[16], t2[16];
    #pragma unroll
    for (int f = 0; f < 16; f++) p[f] = g_pool[g * 16 + f] * inv;

    // Phi head
    layer16x16(p,  t1, Wp1, bp1, true);
    layer16x16(t1, t2, Wp2, bp2, true);
    float phi0 = __ldg(bp3 + 0), phi1 = __ldg(bp3 + 1);
    #pragma unroll
    for (int k = 0; k < 16; k++) {
        phi0 += t2[k] * __ldg(Wp3 + k * 2 + 0);
        phi1 += t2[k] * __ldg(Wp3 + k * 2 + 1);
    }
    // Theta head
    layer16x16(p,  t1, Wt1, bt1, true);
    layer16x16(t1, t2, Wt2, bt2, true);
    float th0 = __ldg(bt3 + 0), th1 = __ldg(bt3 + 1);
    #pragma unroll
    for (int k = 0; k < 16; k++) {
        th0 += t2[k] * __ldg(Wt3 + k * 2 + 0);
        th1 += t2[k] * __ldg(Wt3 + k * 2 + 1);
    }
    out[g * 4 + 0] = phi0;
    out[g * 4 + 1] = phi1;
    out[g * 4 + 2] = th0;
    out[g * 4 + 3] = th1;
}

// ---------------- launch ----------------------------------------------------
extern "C" void kernel_launch(void* const* d_in, const int* in_sizes, int n_in,
                              void* d_out, int out_size) {
    const float* X  = (const float*)d_in[0];
    const int*   EI = (const int*)  d_in[1];
    const float* EW = (const float*)d_in[2];
    const int*   B  = (const int*)  d_in[3];
    // 16 weight/bias tensors are the LAST 16 inputs (num_graphs may or may not
    // appear as an input between Batching and W1).
    int base = n_in - 16;
    const float* W1  = (const float*)d_in[base +  0];
    const float* b1  = (const float*)d_in[base +  1];
    const float* W2  = (const float*)d_in[base +  2];
    const float* b2  = (const float*)d_in[base +  3];
    const float* Wp1 = (const float*)d_in[base +  4];
    const float* bp1 = (const float*)d_in[base +  5];
    const float* Wp2 = (const float*)d_in[base +  6];
    const float* bp2 = (const float*)d_in[base +  7];
    const float* Wp3 = (const float*)d_in[base +  8];
    const float* bp3 = (const float*)d_in[base +  9];
    const float* Wt1 = (const float*)d_in[base + 10];
    const float* bt1 = (const float*)d_in[base + 11];
    const float* Wt2 = (const float*)d_in[base + 12];
    const float* bt2 = (const float*)d_in[base + 13];
    const float* Wt3 = (const float*)d_in[base + 14];
    const float* bt3 = (const float*)d_in[base + 15];

    const int* src = EI;
    const int* dst = EI + EE;

    k_zero    <<<(NN * 4) / 256, 256>>>();
    k_deg     <<<EE / 256,       256>>>(dst, EW);
    k_dinv    <<<NN / 256,       256>>>();
    k_l1      <<<EE / 256,       256>>>(src, dst, EW, X);
    k_out1    <<<NN / 256,       256>>>(X, W1, b1);
    k_l2scat  <<<(EE * 4) / 256, 256>>>(src, dst);
    k_out2pool<<<NN / 256,       256>>>(W2, b2, B);
    k_head    <<<GG / 128,       128>>>(Wp1, bp1, Wp2, bp2, Wp3, bp3,
                                        Wt1, bt1, Wt2, bt2, Wt3, bt3,
                                        (float*)d_out);
}

// round 2
// speedup vs baseline: 1.0969x; 1.0969x over previous
#include <cuda_runtime.h>

#define NN 262144
#define EE 4194304
#define GG 1024

// ---------------- scratch (device globals; no allocation allowed) ----------
__device__ __align__(16) int        g_count[NN];
__device__ __align__(16) int        g_off  [NN];     // exclusive bucket start
__device__ __align__(16) int        g_cur  [NN];     // cursor; == bucket end after build
__device__ __align__(16) int        g_bsum [256];
__device__ __align__(16) long long  g_ebuf [EE];     // packed (w_bits<<32)|src
__device__ __align__(16) float      g_dinv [NN];
__device__ __align__(16) float4     g_y    [NN];     // x * dinv (padded 3->4)
__device__ __align__(16) float      g_z    [NN * 16];// out1 * dinv
__device__ __align__(16) float      g_agg2 [NN * 16];// layer-2 neighbor aggregate
__device__ __align__(16) float      g_pool [GG * 16];
__device__ __align__(16) float      g_cnt  [GG];

__device__ __forceinline__ float leaky(float x) { return x > 0.0f ? x : 0.01f * x; }

__device__ __forceinline__ void red_add_v4(float* p, float a, float b, float c, float d) {
    asm volatile("red.global.add.v4.f32 [%0], {%1,%2,%3,%4};"
                 :: "l"(p), "f"(a), "f"(b), "f"(c), "f"(d) : "memory");
}

// ---------------- K0: zero count + pool ------------------------------------
__global__ void k_zero() {
    int i = blockIdx.x * blockDim.x + threadIdx.x;   // NN threads
    g_count[i] = 0;
    if (i < GG * 16) g_pool[i] = 0.0f;
    if (i < GG)      g_cnt[i]  = 0.0f;
}

// ---------------- K1: per-dst edge counts ----------------------------------
__global__ void k_count(const int* __restrict__ dst) {
    int e = blockIdx.x * blockDim.x + threadIdx.x;
    if (e < EE) atomicAdd(&g_count[dst[e]], 1);
}

// ---------------- K2a/b/c: exclusive prefix scan of counts -----------------
__global__ void k_scanA() {   // 256 blocks x 1024 threads
    __shared__ int sh[1024];
    int t = threadIdx.x;
    int i = blockIdx.x * 1024 + t;
    int v = g_count[i];
    sh[t] = v; __syncthreads();
    #pragma unroll
    for (int o = 1; o < 1024; o <<= 1) {
        int u = (t >= o) ? sh[t - o] : 0;
        __syncthreads();
        sh[t] += u;
        __syncthreads();
    }
    g_off[i] = sh[t] - v;                 // partial exclusive scan
    if (t == 1023) g_bsum[blockIdx.x] = sh[t];
}

__global__ void k_scanB() {   // 1 block x 256 threads
    __shared__ int sh[256];
    int t = threadIdx.x;
    int v = g_bsum[t];
    sh[t] = v; __syncthreads();
    #pragma unroll
    for (int o = 1; o < 256; o <<= 1) {
        int u = (t >= o) ? sh[t - o] : 0;
        __syncthreads();
        sh[t] += u;
        __syncthreads();
    }
    g_bsum[t] = sh[t] - v;                // exclusive
}

__global__ void k_scanC() {   // 256 blocks x 1024 threads
    int i = blockIdx.x * 1024 + threadIdx.x;
    int v = g_off[i] + g_bsum[blockIdx.x];
    g_off[i] = v;
    g_cur[i] = v;
}

// ---------------- K3: bucket edges by dst ----------------------------------
__global__ void k_build(const int* __restrict__ src, const int* __restrict__ dst,
                        const float* __restrict__ ew) {
    int e = blockIdx.x * blockDim.x + threadIdx.x;
    if (e >= EE) return;
    int d = dst[e];
    int pos = atomicAdd(&g_cur[d], 1);
    long long pk = ((long long)__float_as_int(ew[e]) << 32) | (unsigned int)src[e];
    g_ebuf[pos] = pk;
}

// ---------------- K4: weighted degree -> dinv, y = x*dinv ------------------
__global__ void k_prep(const float* __restrict__ X) {
    int i = blockIdx.x * blockDim.x + threadIdx.x;
    if (i >= NN) return;
    int st = g_off[i], en = g_cur[i];
    float deg = 1.0f;                                 // self-loop
    for (int e = st; e < en; e++) {
        long long pk = g_ebuf[e];
        deg += __int_as_float((int)(pk >> 32));
    }
    float di = rsqrtf(deg);
    g_dinv[i] = di;
    g_y[i] = make_float4(X[i * 3 + 0] * di, X[i * 3 + 1] * di, X[i * 3 + 2] * di, 0.0f);
}

// ---------------- K5: layer 1 fused (gather + GEMM + act), z = out1*dinv ---
__global__ void k_l1f(const float* __restrict__ W1, const float* __restrict__ b1) {
    __shared__ float sW[48], sb[16];
    int tid = threadIdx.x;
    if (tid < 48) sW[tid] = W1[tid];
    if (tid < 16) sb[tid] = b1[tid];
    __syncthreads();

    int i = blockIdx.x * blockDim.x + tid;
    if (i >= NN) return;
    int st = g_off[i], en = g_cur[i];
    float4 acc = make_float4(0.f, 0.f, 0.f, 0.f);
    for (int e = st; e < en; e++) {
        long long pk = g_ebuf[e];
        int   s = (int)(pk & 0xffffffff);
        float w = __int_as_float((int)(pk >> 32));
        float4 ys = g_y[s];
        acc.x += w * ys.x; acc.y += w * ys.y; acc.z += w * ys.z;
    }
    float di = g_dinv[i];
    float4 yi = g_y[i];
    float a0 = di * (acc.x + yi.x);
    float a1 = di * (acc.y + yi.y);
    float a2 = di * (acc.z + yi.z);

    float o[16];
    #pragma unroll
    for (int f = 0; f < 16; f++) {
        float v = sb[f] + a0 * sW[0 * 16 + f] + a1 * sW[1 * 16 + f] + a2 * sW[2 * 16 + f];
        o[f] = leaky(v) * di;                         // store z = out1*dinv
    }
    float4* zp = (float4*)(g_z + i * 16);
    #pragma unroll
    for (int q = 0; q < 4; q++)
        zp[q] = make_float4(o[q * 4 + 0], o[q * 4 + 1], o[q * 4 + 2], o[q * 4 + 3]);
}

// ---------------- K6: layer 2 aggregate, 4 threads/node, NO atomics --------
__global__ void k_l2agg() {
    int t = blockIdx.x * blockDim.x + threadIdx.x;    // NN*4 threads
    int i = t >> 2, q = t & 3;
    int st = g_off[i], en = g_cur[i];
    float4 acc = make_float4(0.f, 0.f, 0.f, 0.f);
    for (int e = st; e < en; e++) {
        long long pk = g_ebuf[e];                     // 4 lanes same addr -> broadcast
        int   s = (int)(pk & 0xffffffff);
        float w = __int_as_float((int)(pk >> 32));
        float4 zq = ((const float4*)(g_z + s * 16))[q];
        acc.x += w * zq.x; acc.y += w * zq.y; acc.z += w * zq.z; acc.w += w * zq.w;
    }
    ((float4*)(g_agg2 + i * 16))[q] = acc;            // exclusive slot
}

// ---------------- K7: out2 + mean-pool scatter -----------------------------
__global__ void k_out2pool(const float* __restrict__ W2, const float* __restrict__ b2,
                           const int* __restrict__ batch) {
    __shared__ float sW[256], sb[16];
    int tid = threadIdx.x;
    if (tid < 256) sW[tid] = W2[tid];
    if (tid < 16)  sb[tid] = b2[tid];
    __syncthreads();

    int i = blockIdx.x * blockDim.x + tid;
    if (i >= NN) return;
    float di = g_dinv[i];

    float a[16];
    const float4* pA = (const float4*)(g_agg2 + i * 16);
    const float4* pZ = (const float4*)(g_z    + i * 16);
    #pragma unroll
    for (int q = 0; q < 4; q++) {
        float4 va = pA[q], vz = pZ[q];                // a = dinv*(agg + z_i)
        a[q * 4 + 0] = di * (va.x + vz.x);
        a[q * 4 + 1] = di * (va.y + vz.y);
        a[q * 4 + 2] = di * (va.z + vz.z);
        a[q * 4 + 3] = di * (va.w + vz.w);
    }
    float o[16];
    #pragma unroll
    for (int f = 0; f < 16; f++) {
        float v = sb[f];
        #pragma unroll
        for (int k = 0; k < 16; k++) v += a[k] * sW[k * 16 + f];
        o[f] = leaky(v);
    }
    int b = batch[i];
    float* pp = g_pool + b * 16;
    red_add_v4(pp +  0, o[0],  o[1],  o[2],  o[3]);
    red_add_v4(pp +  4, o[4],  o[5],  o[6],  o[7]);
    red_add_v4(pp +  8, o[8],  o[9],  o[10], o[11]);
    red_add_v4(pp + 12, o[12], o[13], o[14], o[15]);
    atomicAdd(&g_cnt[b], 1.0f);
}

// ---------------- K8: per-graph MLP heads ----------------------------------
__device__ __forceinline__ void layer16x16(const float* in, float* out,
                                           const float* W, const float* b, bool act) {
    #pragma unroll
    for (int f = 0; f < 16; f++) {
        float v = __ldg(b + f);
        #pragma unroll
        for (int k = 0; k < 16; k++) v += in[k] * __ldg(W + k * 16 + f);
        out[f] = act ? leaky(v) : v;
    }
}

__global__ void k_head(const float* __restrict__ Wp1, const float* __restrict__ bp1,
                       const float* __restrict__ Wp2, const float* __restrict__ bp2,
                       const float* __restrict__ Wp3, const float* __restrict__ bp3,
                       const float* __restrict__ Wt1, const float* __restrict__ bt1,
                       const float* __restrict__ Wt2, const float* __restrict__ bt2,
                       const float* __restrict__ Wt3, const float* __restrict__ bt3,
                       float* __restrict__ out) {
    int g = blockIdx.x * blockDim.x + threadIdx.x;
    if (g >= GG) return;
    float inv = 1.0f / fmaxf(g_cnt[g], 1.0f);
    float p[16], t1[16], t2[16];
    #pragma unroll
    for (int f = 0; f < 16; f++) p[f] = g_pool[g * 16 + f] * inv;

    layer16x16(p,  t1, Wp1, bp1, true);
    layer16x16(t1, t2, Wp2, bp2, true);
    float phi0 = __ldg(bp3 + 0), phi1 = __ldg(bp3 + 1);
    #pragma unroll
    for (int k = 0; k < 16; k++) {
        phi0 += t2[k] * __ldg(Wp3 + k * 2 + 0);
        phi1 += t2[k] * __ldg(Wp3 + k * 2 + 1);
    }
    layer16x16(p,  t1, Wt1, bt1, true);
    layer16x16(t1, t2, Wt2, bt2, true);
    float th0 = __ldg(bt3 + 0), th1 = __ldg(bt3 + 1);
    #pragma unroll
    for (int k = 0; k < 16; k++) {
        th0 += t2[k] * __ldg(Wt3 + k * 2 + 0);
        th1 += t2[k] * __ldg(Wt3 + k * 2 + 1);
    }
    out[g * 4 + 0] = phi0;
    out[g * 4 + 1] = phi1;
    out[g * 4 + 2] = th0;
    out[g * 4 + 3] = th1;
}

// ---------------- launch ----------------------------------------------------
extern "C" void kernel_launch(void* const* d_in, const int* in_sizes, int n_in,
                              void* d_out, int out_size) {
    const float* X  = (const float*)d_in[0];
    const int*   EI = (const int*)  d_in[1];
    const float* EW = (const float*)d_in[2];
    const int*   B  = (const int*)  d_in[3];
    int base = n_in - 16;
    const float* W1  = (const float*)d_in[base +  0];
    const float* b1  = (const float*)d_in[base +  1];
    const float* W2  = (const float*)d_in[base +  2];
    const float* b2  = (const float*)d_in[base +  3];
    const float* Wp1 = (const float*)d_in[base +  4];
    const float* bp1 = (const float*)d_in[base +  5];
    const float* Wp2 = (const float*)d_in[base +  6];
    const float* bp2 = (const float*)d_in[base +  7];
    const float* Wp3 = (const float*)d_in[base +  8];
    const float* bp3 = (const float*)d_in[base +  9];
    const float* Wt1 = (const float*)d_in[base + 10];
    const float* bt1 = (const float*)d_in[base + 11];
    const float* Wt2 = (const float*)d_in[base + 12];
    const float* bt2 = (const float*)d_in[base + 13];
    const float* Wt3 = (const float*)d_in[base + 14];
    const float* bt3 = (const float*)d_in[base + 15];

    const int* src = EI;
    const int* dst = EI + EE;

    k_zero     <<<NN / 256,       256>>>();
    k_count    <<<EE / 256,       256>>>(dst);
    k_scanA    <<<256,           1024>>>();
    k_scanB    <<<1,              256>>>();
    k_scanC    <<<256,           1024>>>();
    k_build    <<<EE / 256,       256>>>(src, dst, EW);
    k_prep     <<<NN / 256,       256>>>(X);
    k_l1f      <<<NN / 256,       256>>>(W1, b1);
    k_l2agg    <<<(NN * 4) / 256, 256>>>();
    k_out2pool <<<NN / 256,       256>>>(W2, b2, B);
    k_head     <<<GG / 128,       128>>>(Wp1, bp1, Wp2, bp2, Wp3, bp3,
                                         Wt1, bt1, Wt2, bt2, Wt3, bt3,
                                         (float*)d_out);
}